// round 1
// baseline (speedup 1.0000x reference)
#include <cuda_runtime.h>
#include <math.h>

// Problem constants
#define DM   768
#define BSZ  2
#define NSEQ 2048
#define NH   12
#define DK   64
#define ROWS (BSZ*NSEQ)          // 4096
#define SLOT ((size_t)ROWS*DM)   // 3,145,728 floats

// Scratch: 10 slots
//  0: rgb_n  1: ir_n
//  2: q_vis  3: k_vis  4: v_vis
//  5: q_ir   6: k_ir   7: v_ir
//  8: att0 (MHA(q_ir,k_vis,v_vis))   9: att1 (MHA(q_vis,k_ir,v_ir))
__device__ float g_scratch[10 * SLOT];

// ---------------------------------------------------------------------------
// LayerNorm: one block per row; row < ROWS -> rgb w/ ln0, else ir w/ ln1
// ---------------------------------------------------------------------------
__global__ __launch_bounds__(256) void ln_kernel(
    const float* __restrict__ rgb, const float* __restrict__ ir,
    const float* __restrict__ w0, const float* __restrict__ b0,
    const float* __restrict__ w1, const float* __restrict__ b1,
    float* __restrict__ out_rgbn, float* __restrict__ out_irn)
{
    int row = blockIdx.x;
    const float* x; float* y; const float* w; const float* b;
    if (row < ROWS) { x = rgb + (size_t)row*DM; y = out_rgbn + (size_t)row*DM; w = w0; b = b0; }
    else { row -= ROWS; x = ir + (size_t)row*DM; y = out_irn + (size_t)row*DM; w = w1; b = b1; }

    int t = threadIdx.x;
    float v0 = x[t], v1 = x[t+256], v2 = x[t+512];
    float s  = v0+v1+v2;
    float sq = v0*v0 + v1*v1 + v2*v2;

    #pragma unroll
    for (int o = 16; o > 0; o >>= 1) {
        s  += __shfl_xor_sync(0xffffffffu, s,  o);
        sq += __shfl_xor_sync(0xffffffffu, sq, o);
    }
    __shared__ float shs[8], shq[8];
    int warp = t >> 5, lane = t & 31;
    if (lane == 0) { shs[warp] = s; shq[warp] = sq; }
    __syncthreads();
    float ts = 0.f, tq = 0.f;
    #pragma unroll
    for (int i = 0; i < 8; i++) { ts += shs[i]; tq += shq[i]; }

    const float inv = 1.0f / (float)DM;
    float mean = ts * inv;
    float var  = tq * inv - mean*mean;
    float rstd = rsqrtf(var + 1e-5f);

    y[t]     = (v0 - mean)*rstd*w[t]     + b[t];
    y[t+256] = (v1 - mean)*rstd*w[t+256] + b[t+256];
    y[t+512] = (v2 - mean)*rstd*w[t+512] + b[t+512];
}

// ---------------------------------------------------------------------------
// GEMM + bias: C[M,Nn] = A[M,K] @ W[K,Nn] + bias
// BM=128, BN=64, BK=16, 256 threads, 8x4 register tile per thread.
// Requires M%128==0, Nn%64==0, K%16==0 (true here: 4096, 768, 768).
// ---------------------------------------------------------------------------
#define BM 128
#define BN 64
#define BK 16
__global__ __launch_bounds__(256) void gemm_bias(
    const float* __restrict__ A, const float* __restrict__ W,
    const float* __restrict__ bias, float* __restrict__ C,
    int M, int Nn, int K)
{
    __shared__ float As[BK][BM];
    __shared__ float Bs[BK][BN];

    int t  = threadIdx.x;
    int tx = t & 15;          // 0..15 -> col group (4 cols)
    int ty = t >> 4;          // 0..15 -> row group (8 rows)
    int bx = blockIdx.x;      // N tile
    int by = blockIdx.y;      // M tile

    // A tile loads: thread -> row (t>>2) & (t>>2)+64, col4 = (t&3)*4
    int arow = t >> 2;
    int acol = (t & 3) * 4;
    // B tile loads: thread -> row t>>4, col4 = (t&15)*4
    int brow = t >> 4;
    int bcol = (t & 15) * 4;

    const float* Aptr = A + (size_t)(by*BM + arow)*K + acol;
    const float* Wptr = W + (size_t)brow*Nn + bx*BN + bcol;

    float acc[8][4];
    #pragma unroll
    for (int i = 0; i < 8; i++)
        #pragma unroll
        for (int j = 0; j < 4; j++) acc[i][j] = 0.f;

    for (int k0 = 0; k0 < K; k0 += BK) {
        float4 a0 = *(const float4*)(Aptr);
        float4 a1 = *(const float4*)(Aptr + (size_t)64*K);
        float4 bv = *(const float4*)(Wptr);

        As[acol+0][arow]    = a0.x;
        As[acol+1][arow]    = a0.y;
        As[acol+2][arow]    = a0.z;
        As[acol+3][arow]    = a0.w;
        As[acol+0][arow+64] = a1.x;
        As[acol+1][arow+64] = a1.y;
        As[acol+2][arow+64] = a1.z;
        As[acol+3][arow+64] = a1.w;
        *(float4*)&Bs[brow][bcol] = bv;
        __syncthreads();

        #pragma unroll
        for (int kk = 0; kk < BK; kk++) {
            float4 a0r = *(const float4*)&As[kk][ty*8];
            float4 a1r = *(const float4*)&As[kk][ty*8+4];
            float4 br  = *(const float4*)&Bs[kk][tx*4];
            float ar[8] = {a0r.x,a0r.y,a0r.z,a0r.w,a1r.x,a1r.y,a1r.z,a1r.w};
            float brr[4] = {br.x,br.y,br.z,br.w};
            #pragma unroll
            for (int i = 0; i < 8; i++)
                #pragma unroll
                for (int j = 0; j < 4; j++)
                    acc[i][j] = fmaf(ar[i], brr[j], acc[i][j]);
        }
        __syncthreads();

        Aptr += BK;
        Wptr += (size_t)BK * Nn;
    }

    int crow = by*BM + ty*8;
    int ccol = bx*BN + tx*4;
    float4 b4 = *(const float4*)(bias + ccol);
    #pragma unroll
    for (int i = 0; i < 8; i++) {
        float4 o;
        o.x = acc[i][0] + b4.x;
        o.y = acc[i][1] + b4.y;
        o.z = acc[i][2] + b4.z;
        o.w = acc[i][3] + b4.w;
        *(float4*)(C + (size_t)(crow+i)*Nn + ccol) = o;
    }
}

// ---------------------------------------------------------------------------
// Flash attention (fp32): grid (NSEQ/64, NH, BSZ), 64 threads.
// Thread t owns query row blockIdx.x*64+t: q and o accumulators in registers,
// key tiles of 16 staged in smem, online softmax.
// ---------------------------------------------------------------------------
#define BR 64
#define BC 16
__global__ __launch_bounds__(64) void attn_kernel(
    const float* __restrict__ Qg, const float* __restrict__ Kg,
    const float* __restrict__ Vg, float* __restrict__ Og)
{
    __shared__ float4 Ks[BC][DK/4];
    __shared__ float4 Vs[BC][DK/4];

    int t = threadIdx.x;
    int b = blockIdx.z;
    int h = blockIdx.y;
    int qrow = blockIdx.x * BR + t;

    const size_t headoff = (size_t)h * DK;
    const float* qptr = Qg + ((size_t)(b*NSEQ) + qrow)*DM + headoff;

    const float scale = 0.125f;   // 1/sqrt(64)
    float4 q[DK/4];
    #pragma unroll
    for (int d4 = 0; d4 < DK/4; d4++) {
        float4 v = *(const float4*)(qptr + d4*4);
        v.x *= scale; v.y *= scale; v.z *= scale; v.w *= scale;
        q[d4] = v;
    }

    float m = -INFINITY, l = 0.f;
    float4 o[DK/4];
    #pragma unroll
    for (int d4 = 0; d4 < DK/4; d4++) o[d4] = make_float4(0.f,0.f,0.f,0.f);

    for (int kt = 0; kt < NSEQ/BC; kt++) {
        // stage K,V tile (16 rows x 64 cols)
        #pragma unroll
        for (int i = 0; i < 4; i++) {
            int idx = t + i*64;       // 0..255
            int row = idx >> 4;
            int d4  = idx & 15;
            size_t goff = ((size_t)(b*NSEQ) + kt*BC + row)*DM + headoff;
            Ks[row][d4] = *(const float4*)(Kg + goff + d4*4);
            Vs[row][d4] = *(const float4*)(Vg + goff + d4*4);
        }
        __syncthreads();

        float s[BC];
        #pragma unroll
        for (int j = 0; j < BC; j++) {
            float acc = 0.f;
            #pragma unroll
            for (int d4 = 0; d4 < DK/4; d4++) {
                float4 kv = Ks[j][d4];
                acc = fmaf(q[d4].x, kv.x, acc);
                acc = fmaf(q[d4].y, kv.y, acc);
                acc = fmaf(q[d4].z, kv.z, acc);
                acc = fmaf(q[d4].w, kv.w, acc);
            }
            s[j] = acc;
        }

        float m_new = m;
        #pragma unroll
        for (int j = 0; j < BC; j++) m_new = fmaxf(m_new, s[j]);
        float corr = __expf(m - m_new);
        float p[BC];
        float psum = 0.f;
        #pragma unroll
        for (int j = 0; j < BC; j++) { p[j] = __expf(s[j] - m_new); psum += p[j]; }
        l = l * corr + psum;
        #pragma unroll
        for (int d4 = 0; d4 < DK/4; d4++) {
            o[d4].x *= corr; o[d4].y *= corr; o[d4].z *= corr; o[d4].w *= corr;
        }
        #pragma unroll
        for (int j = 0; j < BC; j++) {
            float pj = p[j];
            #pragma unroll
            for (int d4 = 0; d4 < DK/4; d4++) {
                float4 v = Vs[j][d4];
                o[d4].x = fmaf(pj, v.x, o[d4].x);
                o[d4].y = fmaf(pj, v.y, o[d4].y);
                o[d4].z = fmaf(pj, v.z, o[d4].z);
                o[d4].w = fmaf(pj, v.w, o[d4].w);
            }
        }
        m = m_new;
        __syncthreads();
    }

    float inv_l = 1.0f / l;
    float* optr = Og + ((size_t)(b*NSEQ) + qrow)*DM + headoff;
    #pragma unroll
    for (int d4 = 0; d4 < DK/4; d4++) {
        float4 v = o[d4];
        v.x *= inv_l; v.y *= inv_l; v.z *= inv_l; v.w *= inv_l;
        *(float4*)(optr + d4*4) = v;
    }
}

// ---------------------------------------------------------------------------
// Launch
// ---------------------------------------------------------------------------
extern "C" void kernel_launch(void* const* d_in, const int* in_sizes, int n_in,
                              void* d_out, int out_size)
{
    const float* rgb    = (const float*)d_in[0];
    const float* ir     = (const float*)d_in[1];
    const float* ln0_w  = (const float*)d_in[2];
    const float* ln0_b  = (const float*)d_in[3];
    const float* ln1_w  = (const float*)d_in[4];
    const float* ln1_b  = (const float*)d_in[5];
    const float* Wq_vis = (const float*)d_in[6];
    const float* bq_vis = (const float*)d_in[7];
    const float* Wk_vis = (const float*)d_in[8];
    const float* bk_vis = (const float*)d_in[9];
    const float* Wq_ir  = (const float*)d_in[10];
    const float* bq_ir  = (const float*)d_in[11];
    const float* Wk_ir  = (const float*)d_in[12];
    const float* bk_ir  = (const float*)d_in[13];
    const float* Wv_vis = (const float*)d_in[14];
    const float* bv_vis = (const float*)d_in[15];
    const float* Wv_ir  = (const float*)d_in[16];
    const float* bv_ir  = (const float*)d_in[17];
    const float* Wo_vis = (const float*)d_in[18];
    const float* bo_vis = (const float*)d_in[19];
    const float* Wo_ir  = (const float*)d_in[20];
    const float* bo_ir  = (const float*)d_in[21];
    float* out = (float*)d_out;

    float* scr = nullptr;
    cudaGetSymbolAddress((void**)&scr, g_scratch);
    float* rgbn = scr + 0*SLOT;
    float* irn  = scr + 1*SLOT;
    float* qvis = scr + 2*SLOT;
    float* kvis = scr + 3*SLOT;
    float* vvis = scr + 4*SLOT;
    float* qir  = scr + 5*SLOT;
    float* kir  = scr + 6*SLOT;
    float* vir  = scr + 7*SLOT;
    float* att0 = scr + 8*SLOT;
    float* att1 = scr + 9*SLOT;

    // 1. LayerNorms (both modalities in one launch)
    ln_kernel<<<2*ROWS, 256>>>(rgb, ir, ln0_w, ln0_b, ln1_w, ln1_b, rgbn, irn);

    // 2. Projections
    dim3 ggrid(DM/BN, ROWS/BM);   // (12, 32)
    gemm_bias<<<ggrid, 256>>>(rgbn, Wq_vis, bq_vis, qvis, ROWS, DM, DM);
    gemm_bias<<<ggrid, 256>>>(rgbn, Wk_vis, bk_vis, kvis, ROWS, DM, DM);
    gemm_bias<<<ggrid, 256>>>(rgbn, Wv_vis, bv_vis, vvis, ROWS, DM, DM);
    gemm_bias<<<ggrid, 256>>>(irn,  Wq_ir,  bq_ir,  qir,  ROWS, DM, DM);
    gemm_bias<<<ggrid, 256>>>(irn,  Wk_ir,  bk_ir,  kir,  ROWS, DM, DM);
    gemm_bias<<<ggrid, 256>>>(irn,  Wv_ir,  bv_ir,  vir,  ROWS, DM, DM);

    // 3. Cross-attention
    dim3 agrid(NSEQ/BR, NH, BSZ); // (32, 12, 2)
    attn_kernel<<<agrid, BR>>>(qir,  kvis, vvis, att0);  // -> out_vis path
    attn_kernel<<<agrid, BR>>>(qvis, kir,  vir,  att1);  // -> out_ir path

    // 4. Output projections straight into d_out (out_vis then out_ir)
    gemm_bias<<<ggrid, 256>>>(att0, Wo_vis, bo_vis, out,              ROWS, DM, DM);
    gemm_bias<<<ggrid, 256>>>(att1, Wo_ir,  bo_ir,  out + SLOT,       ROWS, DM, DM);
}